// round 3
// baseline (speedup 1.0000x reference)
#include <cuda_runtime.h>
#include <cstdint>

// ============================================================================
// out[8192,4096] = sign(x[8192,4096]) @ sign(w[4096,4096])
// Plan: binarize to int8 (+/-1) into tile-contiguous, bank-swizzled scratch,
// then Ampere-style mma.sync s8 GEMM (exact integer accumulation).
// NOTE: harness compiles via compute_103 (NOT sm_103a) -> no tcgen05/TMA-'a'
// features. mma.sync/cp.async are plain sm_80+ PTX and compile fine.
// ============================================================================

static constexpr int MDIM = 8192;
static constexpr int NDIM = 4096;
static constexpr int KDIM = 4096;

static constexpr int BM = 128;
static constexpr int BN = 256;
static constexpr int BK = 64;

static constexpr int MT = MDIM / BM;   // 64
static constexpr int NT = NDIM / BN;   // 16
static constexpr int KT = KDIM / BK;   // 64

static constexpr int A_TILE = BM * BK;          // 8192 B
static constexpr int B_TILE = BN * BK;          // 16384 B
static constexpr int STAGE  = A_TILE + B_TILE;  // 24576 B
static constexpr int STAGES = 4;
static constexpr int SMEM_TOTAL = STAGES * STAGE;  // 98304 B

// Tile-contiguous int8 sign scratch (pre-swizzled for conflict-free LDS).
__device__ __align__(16) unsigned char g_xa[(size_t)MT * KT * A_TILE];  // 32 MB
__device__ __align__(16) unsigned char g_wb[(size_t)NT * KT * B_TILE];  // 16 MB

// ---------------------------------------------------------------------------
// Swizzled byte offset of word w (0..15) in row r of a 64-byte-row tile.
// 16B-chunk swizzle: chunk' = chunk ^ ((r ^ (r>>2)) & 3). Conflict-free for
// the mma fragment access patterns (8 rows x 4 tig lanes per LDS).
__device__ __host__ __forceinline__ uint32_t swoff(int r, int w) {
    int chunk = w >> 2;
    int sw = chunk ^ ((r ^ (r >> 2)) & 3);
    return (uint32_t)(r * 64 + (sw << 4) + ((w & 3) << 2));
}

__device__ __forceinline__ uint32_t smem_u32(const void* p) {
    uint32_t a;
    asm("{ .reg .u64 t; cvta.to.shared.u64 t, %1; cvt.u32.u64 %0, t; }" : "=r"(a) : "l"(p));
    return a;
}

__device__ __forceinline__ uint32_t lds32(uint32_t addr) {
    uint32_t v;
    asm volatile("ld.shared.u32 %0, [%1];" : "=r"(v) : "r"(addr));
    return v;
}

__device__ __forceinline__ void cpasync16(uint32_t s, const void* g) {
    asm volatile("cp.async.cg.shared.global [%0], [%1], 16;" :: "r"(s), "l"(g));
}

#define CP_COMMIT() asm volatile("cp.async.commit_group;" ::: "memory")
#define CP_WAIT2()  asm volatile("cp.async.wait_group 2;" ::: "memory")

__device__ __forceinline__ void mma_s8(int* c, const uint32_t* a, const uint32_t* b) {
    asm volatile(
        "mma.sync.aligned.m16n8k32.row.col.s32.s8.s8.s32 "
        "{%0,%1,%2,%3}, {%4,%5,%6,%7}, {%8,%9}, {%0,%1,%2,%3};"
        : "+r"(c[0]), "+r"(c[1]), "+r"(c[2]), "+r"(c[3])
        : "r"(a[0]), "r"(a[1]), "r"(a[2]), "r"(a[3]), "r"(b[0]), "r"(b[1]));
}

__device__ __forceinline__ unsigned char s8sign(float v) {
    return (v >= 0.0f) ? (unsigned char)0x01 : (unsigned char)0xFF;  // +1 / -1
}

// ---------------------------------------------------------------------------
// Prepass 1: binarize x -> g_xa, tile-contiguous [mt][kt][128 x 64B] swizzled.
// Thread: 4 consecutive k (float4 read) -> one 4B word at swizzled position.
// ---------------------------------------------------------------------------
__global__ void __launch_bounds__(256) k_binx(const float* __restrict__ x) {
    uint32_t q = blockIdx.x * 256u + threadIdx.x;   // 0 .. 8192*1024-1
    uint32_t m = q >> 10;                            // row
    uint32_t w = q & 1023u;                          // word within row (4 k each)
    float4 v = *reinterpret_cast<const float4*>(x + (size_t)m * KDIM + (size_t)w * 4u);
    uint32_t word = (uint32_t)s8sign(v.x)
                  | ((uint32_t)s8sign(v.y) << 8)
                  | ((uint32_t)s8sign(v.z) << 16)
                  | ((uint32_t)s8sign(v.w) << 24);
    uint32_t kt = w >> 4, wl = w & 15u;
    size_t tile = ((size_t)((m >> 7) * (uint32_t)KT + kt)) * (size_t)A_TILE;
    *reinterpret_cast<uint32_t*>(g_xa + tile + swoff((int)(m & 127u), (int)wl)) = word;
}

// ---------------------------------------------------------------------------
// Prepass 2: binarize + transpose w -> g_wb, tiles [nt][kt][256 x 64B] (row=n,
// bytes=k) swizzled. Coalesced reads along n, smem transpose.
// ---------------------------------------------------------------------------
__global__ void __launch_bounds__(256) k_binw(const float* __restrict__ w) {
    __shared__ unsigned char s[256][68];  // [n_local][k_local], padded row
    uint32_t bid = blockIdx.x;
    uint32_t nt = bid & (uint32_t)(NT - 1);
    uint32_t kt = bid >> 4;
    uint32_t n0 = nt * 256u, k0 = kt * 64u;

    #pragma unroll
    for (int it = 0; it < 16; it++) {
        uint32_t q = threadIdx.x + it * 256u;        // 0..4095
        uint32_t kl = q >> 6;                         // 0..63
        uint32_t nl = (q & 63u) << 2;                 // 0..252
        float4 v = *reinterpret_cast<const float4*>(
            w + (size_t)(k0 + kl) * NDIM + n0 + nl);
        s[nl + 0][kl] = s8sign(v.x);
        s[nl + 1][kl] = s8sign(v.y);
        s[nl + 2][kl] = s8sign(v.z);
        s[nl + 3][kl] = s8sign(v.w);
    }
    __syncthreads();

    size_t tile = ((size_t)(nt * (uint32_t)KT + kt)) * (size_t)B_TILE;
    #pragma unroll
    for (int it = 0; it < 16; it++) {
        uint32_t idx = threadIdx.x + it * 256u;      // word index 0..4095
        uint32_t r = idx >> 4, wd = idx & 15u;
        uint32_t word = *reinterpret_cast<const uint32_t*>(&s[r][wd * 4]);
        *reinterpret_cast<uint32_t*>(g_wb + tile + swoff((int)r, (int)wd)) = word;
    }
}

// ---------------------------------------------------------------------------
// GEMM: BM=128 x BN=256 x BK=64, 256 threads (8 warps, 2x4, warp tile 64x64),
// 4-stage cp.async pipeline, s8 mma.sync, exact s32->f32 epilogue.
// ---------------------------------------------------------------------------
__global__ void __launch_bounds__(256, 1) k_gemm(float* __restrict__ out) {
    extern __shared__ unsigned char smem[];
    const uint32_t sb = smem_u32(smem);
    const int tid  = threadIdx.x;
    const int warp = tid >> 5;
    const int lane = tid & 31;
    const int g    = lane >> 2;     // group id (row within fragment)
    const int tig  = lane & 3;      // thread in group
    const int mbase = (warp >> 2) * 64;   // warp_m in {0,1}
    const int nbase = (warp & 3) * 64;    // warp_n in {0..3}

    const uint32_t bid = blockIdx.x;
    const uint32_t nt = bid & (uint32_t)(NT - 1);
    const uint32_t mt = bid >> 4;

    const unsigned char* aP = g_xa + (size_t)(mt * (uint32_t)KT) * (size_t)A_TILE;
    const unsigned char* bP = g_wb + (size_t)(nt * (uint32_t)KT) * (size_t)B_TILE;

    int acc[4][8][4];
    #pragma unroll
    for (int mf = 0; mf < 4; mf++)
        #pragma unroll
        for (int nf = 0; nf < 8; nf++)
            #pragma unroll
            for (int i = 0; i < 4; i++) acc[mf][nf][i] = 0;

    auto load_stage = [&](int s, int kt) {
        uint32_t base = sb + (uint32_t)(s * STAGE);
        const unsigned char* as = aP + (size_t)kt * A_TILE;
        const unsigned char* bs = bP + (size_t)kt * B_TILE;
        #pragma unroll
        for (int i = 0; i < 2; i++) {               // A: 512 chunks of 16B
            int c = tid + i * 256;
            cpasync16(base + (uint32_t)(c * 16), as + (size_t)c * 16);
        }
        #pragma unroll
        for (int i = 0; i < 4; i++) {               // B: 1024 chunks of 16B
            int c = tid + i * 256;
            cpasync16(base + (uint32_t)A_TILE + (uint32_t)(c * 16), bs + (size_t)c * 16);
        }
    };

    load_stage(0, 0); CP_COMMIT();
    load_stage(1, 1); CP_COMMIT();
    load_stage(2, 2); CP_COMMIT();

    for (int kt = 0; kt < KT; kt++) {
        CP_WAIT2();
        __syncthreads();

        // Refill the stage consumed at kt-1 (all threads are past it).
        if (kt + 3 < KT) load_stage((kt + 3) & 3, kt + 3);
        CP_COMMIT();

        const uint32_t base = sb + (uint32_t)((kt & 3) * STAGE);
        const uint32_t baseB = base + (uint32_t)A_TILE;

        #pragma unroll
        for (int kf = 0; kf < 2; kf++) {
            // Fragment word indices within a 64B (16-word) k-row:
            //   reg 0/1: word = kf*8 + tig       (k bytes kf*32 + tig*4)
            //   reg 2/3: word = kf*8 + 4 + tig   (k bytes kf*32 + 16 + tig*4)
            const int w0 = kf * 8 + tig;
            const int w1 = kf * 8 + 4 + tig;
            uint32_t a[4][4];
            #pragma unroll
            for (int mf = 0; mf < 4; mf++) {
                int r0 = mbase + mf * 16 + g;
                a[mf][0] = lds32(base + swoff(r0,     w0));
                a[mf][1] = lds32(base + swoff(r0 + 8, w0));
                a[mf][2] = lds32(base + swoff(r0,     w1));
                a[mf][3] = lds32(base + swoff(r0 + 8, w1));
            }
            uint32_t b[8][2];
            #pragma unroll
            for (int nf = 0; nf < 8; nf++) {
                int r = nbase + nf * 8 + g;
                b[nf][0] = lds32(baseB + swoff(r, w0));
                b[nf][1] = lds32(baseB + swoff(r, w1));
            }
            #pragma unroll
            for (int mf = 0; mf < 4; mf++)
                #pragma unroll
                for (int nf = 0; nf < 8; nf++)
                    mma_s8(acc[mf][nf], a[mf], b[nf]);
        }
        __syncthreads();
    }

    // Epilogue: exact s32 -> f32, vectorized float2 stores.
    #pragma unroll
    for (int mf = 0; mf < 4; mf++) {
        int row = (int)(mt * 128u) + mbase + mf * 16 + g;
        float* o0 = out + (size_t)row * NDIM + nt * 256u + (uint32_t)(nbase + tig * 2);
        float* o1 = o0 + (size_t)8 * NDIM;
        #pragma unroll
        for (int nf = 0; nf < 8; nf++) {
            *reinterpret_cast<float2*>(o0 + nf * 8) =
                make_float2((float)acc[mf][nf][0], (float)acc[mf][nf][1]);
            *reinterpret_cast<float2*>(o1 + nf * 8) =
                make_float2((float)acc[mf][nf][2], (float)acc[mf][nf][3]);
        }
    }
}

// ---------------------------------------------------------------------------
// Launch
// ---------------------------------------------------------------------------
extern "C" void kernel_launch(void* const* d_in, const int* in_sizes, int n_in,
                              void* d_out, int out_size) {
    const float* x = (const float*)d_in[0];   // [8192, 4096]
    const float* w = (const float*)d_in[1];   // [4096, 4096]
    float* out = (float*)d_out;               // [8192, 4096]
    (void)in_sizes; (void)n_in; (void)out_size;

    cudaFuncSetAttribute(k_gemm, cudaFuncAttributeMaxDynamicSharedMemorySize, SMEM_TOTAL);

    k_binx<<<(MDIM * KDIM / 4) / 256, 256>>>(x);     // 32768 blocks
    k_binw<<<NT * KT, 256>>>(w);                     // 1024 blocks
    k_gemm<<<MT * NT, 256, SMEM_TOTAL>>>(out);       // 1024 blocks
}

// round 6
// speedup vs baseline: 1.8620x; 1.8620x over previous
#include <cuda_runtime.h>
#include <cstdint>

// ============================================================================
// out[8192,4096] = sign(x[8192,4096]) @ sign(w[4096,4096])
//
// Round-5 strategy: bit-pack signs (1 = negative), then binary GEMM on the
// ALU pipe:  dot = K - 2*popc(xbits ^ wbits).  Exact integer arithmetic.
// Legacy mma.sync on sm_103 is microcoded (~60 cyc/issue measured R3);
// XOR + CSA-compressed popcount on the rt=2 ALU pipe is ~2x faster.
// ============================================================================

static constexpr int MDIM = 8192;
static constexpr int NDIM = 4096;
static constexpr int KDIM = 4096;
static constexpr int KW   = KDIM / 32;   // 128 words per row

// GEMM tiling
static constexpr int BM = 64, BN = 64;
static constexpr int MT = MDIM / BM;     // 128
static constexpr int NT = NDIM / BN;     // 64
static constexpr int CHUNK_W = 32;       // words per K-chunk
static constexpr int NCHUNK  = KW / CHUNK_W;  // 4
static constexpr int CHUNK_WORDS = CHUNK_W * 64;  // 2048 words = 8KB per matrix

// Packed bit scratch, tile-chunk-transposed for conflict-free smem loads:
//   x_bits[mt][c][w][m]  (mt<128, c<4, w<32, m<64)
//   w_bits[nt][c][w][n]  (nt<64)
__device__ __align__(16) uint32_t g_xbits[(size_t)MT * KW * 64];   // 4 MB
__device__ __align__(16) uint32_t g_wbits[(size_t)NT * KW * 64];   // 2 MB

// ---------------------------------------------------------------------------
__device__ __forceinline__ uint32_t smem_u32(const void* p) {
    uint32_t a;
    asm("{ .reg .u64 t; cvta.to.shared.u64 t, %1; cvt.u32.u64 %0, t; }" : "=r"(a) : "l"(p));
    return a;
}
__device__ __forceinline__ void cpasync16(uint32_t s, const void* g) {
    asm volatile("cp.async.cg.shared.global [%0], [%1], 16;" :: "r"(s), "l"(g));
}
#define CP_COMMIT() asm volatile("cp.async.commit_group;" ::: "memory")
#define CP_WAITN(n) asm volatile("cp.async.wait_group %0;" :: "n"(n) : "memory")

// ---------------------------------------------------------------------------
// Pack x: one warp per row; ballot packs 32 signs per iteration.
// grid 1024 x 256 (8 warps/block, warp = row).
// ---------------------------------------------------------------------------
__global__ void __launch_bounds__(256) k_packx(const float* __restrict__ x) {
    int m    = blockIdx.x * 8 + (threadIdx.x >> 5);
    int lane = threadIdx.x & 31;
    const float* row = x + (size_t)m * KDIM;
    uint32_t mt = (uint32_t)m >> 6, ml = (uint32_t)m & 63u;
    #pragma unroll 4
    for (int w = 0; w < KW; w++) {
        float v = row[w * 32 + lane];
        uint32_t bits = __ballot_sync(0xffffffffu, v < 0.0f);
        if (lane == 0)
            g_xbits[((size_t)(mt * 4u + ((uint32_t)w >> 5)) * 32u + ((uint32_t)w & 31u)) * 64u + ml] = bits;
    }
}

// ---------------------------------------------------------------------------
// Pack w transposed: thread builds one word (column n, 32 consecutive k).
// Layout index == linear thread index by construction.
// ---------------------------------------------------------------------------
__global__ void __launch_bounds__(256) k_packw(const float* __restrict__ w) {
    uint32_t q  = blockIdx.x * 256u + threadIdx.x;   // 524288 threads
    uint32_t nl = q & 63u;
    uint32_t wi = (q >> 6) & 31u;
    uint32_t c  = (q >> 11) & 3u;
    uint32_t nt = q >> 13;
    uint32_t n  = nt * 64u + nl;
    uint32_t kb = (c * 32u + wi) * 32u;
    uint32_t bits = 0;
    #pragma unroll
    for (int j = 0; j < 32; j++) {
        float v = w[(size_t)(kb + j) * NDIM + n];
        bits |= (v < 0.0f ? 1u : 0u) << j;
    }
    g_wbits[q] = bits;
}

// ---------------------------------------------------------------------------
// Binary GEMM: 64x64 tile per block, 256 threads, 16 outputs/thread (4m x 4n).
// K processed in 4 chunks of 32 words, double-buffered cp.async.
// Per 4 words per output: CSA(ones,x0,x1), CSA(ones,x2,x3), CSA(twos,t0,t1),
// acc += popc(fours-term).  Final: D = 4*acc + 2*popc(twos) + popc(ones).
// ---------------------------------------------------------------------------
__global__ void __launch_bounds__(256, 1) k_bgemm(float* __restrict__ out) {
    __shared__ uint32_t sm[2][2 * CHUNK_WORDS];   // [buf][A 2048 | B 2048]
    const uint32_t sb = smem_u32(sm);

    const int tid  = threadIdx.x;
    const int warp = tid >> 5;
    const int lane = tid & 31;
    const int wm = warp >> 2;        // 0..1
    const int wn = warp & 3;         // 0..3
    const int mi = lane >> 2;        // 0..7
    const int ni = lane & 3;         // 0..3

    const uint32_t bid = blockIdx.x;
    const uint32_t ntb = bid & 63u;          // n tile
    const uint32_t mtb = bid >> 6;           // m tile

    const uint32_t* aG = g_xbits + (size_t)mtb * (KW * 64);
    const uint32_t* bG = g_wbits + (size_t)ntb * (KW * 64);

    // CSA state per output
    uint32_t ones[16], twos[16];
    int acc[16];
    #pragma unroll
    for (int o = 0; o < 16; o++) { ones[o] = 0; twos[o] = 0; acc[o] = 0; }

    auto load_chunk = [&](int buf, int c) {
        uint32_t base = sb + (uint32_t)(buf * 2 * CHUNK_WORDS * 4);
        const char* as = (const char*)(aG + (size_t)c * CHUNK_WORDS);
        const char* bs = (const char*)(bG + (size_t)c * CHUNK_WORDS);
        #pragma unroll
        for (int i = 0; i < 2; i++) {
            int q = tid + i * 256;                       // 0..511 (16B units)
            cpasync16(base + (uint32_t)(q * 16), as + (size_t)q * 16);
            cpasync16(base + (uint32_t)(CHUNK_WORDS * 4) + (uint32_t)(q * 16),
                      bs + (size_t)q * 16);
        }
    };

    load_chunk(0, 0); CP_COMMIT();
    load_chunk(1, 1); CP_COMMIT();

    const int mrow = wm * 32 + mi * 4;   // first of 4 m rows
    const int ncol = wn * 16 + ni * 4;   // first of 4 n cols

    for (int c = 0; c < NCHUNK; c++) {
        CP_WAITN(1);
        __syncthreads();

        const uint32_t* A = sm[c & 1];
        const uint32_t* B = sm[c & 1] + CHUNK_WORDS;

        #pragma unroll
        for (int grp = 0; grp < CHUNK_W / 4; grp++) {
            uint32_t av[4][4], bv[4][4];
            #pragma unroll
            for (int w4 = 0; w4 < 4; w4++) {
                int w = grp * 4 + w4;
                #pragma unroll
                for (int mf = 0; mf < 4; mf++) av[mf][w4] = A[w * 64 + mrow + mf];
                #pragma unroll
                for (int nf = 0; nf < 4; nf++) bv[nf][w4] = B[w * 64 + ncol + nf];
            }
            #pragma unroll
            for (int mf = 0; mf < 4; mf++) {
                #pragma unroll
                for (int nf = 0; nf < 4; nf++) {
                    const int o = mf * 4 + nf;
                    uint32_t x0 = av[mf][0] ^ bv[nf][0];
                    uint32_t x1 = av[mf][1] ^ bv[nf][1];
                    uint32_t x2 = av[mf][2] ^ bv[nf][2];
                    uint32_t x3 = av[mf][3] ^ bv[nf][3];
                    // CSA(ones, x0, x1) -> t0  (maj + xor, LOP3-fusable forms)
                    uint32_t t0 = (ones[o] & x0) | (ones[o] & x1) | (x0 & x1);
                    ones[o] = ones[o] ^ x0 ^ x1;
                    // CSA(ones, x2, x3) -> t1
                    uint32_t t1 = (ones[o] & x2) | (ones[o] & x3) | (x2 & x3);
                    ones[o] = ones[o] ^ x2 ^ x3;
                    // CSA(twos, t0, t1) -> f (weight 4)
                    uint32_t f = (twos[o] & t0) | (twos[o] & t1) | (t0 & t1);
                    twos[o] = twos[o] ^ t0 ^ t1;
                    acc[o] += __popc(f);
                }
            }
        }

        __syncthreads();
        if (c + 2 < NCHUNK) load_chunk(c & 1, c + 2);
        CP_COMMIT();
    }

    // Epilogue: D (disagreements) = 4*acc + 2*popc(twos) + popc(ones);
    // dot = 4096 - 2*D.  Exact s32 -> f32.
    const uint32_t m0 = mtb * 64u + (uint32_t)mrow;
    const uint32_t n0 = ntb * 64u + (uint32_t)ncol;
    #pragma unroll
    for (int mf = 0; mf < 4; mf++) {
        float* orow = out + (size_t)(m0 + (uint32_t)mf) * NDIM + n0;
        #pragma unroll
        for (int nf = 0; nf < 4; nf++) {
            const int o = mf * 4 + nf;
            int D = (acc[o] << 2) + (__popc(twos[o]) << 1) + __popc(ones[o]);
            orow[nf] = (float)(KDIM - 2 * D);
        }
    }
}

// ---------------------------------------------------------------------------
// Launch
// ---------------------------------------------------------------------------
extern "C" void kernel_launch(void* const* d_in, const int* in_sizes, int n_in,
                              void* d_out, int out_size) {
    const float* x = (const float*)d_in[0];   // [8192, 4096]
    const float* w = (const float*)d_in[1];   // [4096, 4096] (k-major)
    float* out = (float*)d_out;               // [8192, 4096]
    (void)in_sizes; (void)n_in; (void)out_size;

    k_packx<<<MDIM / 8, 256>>>(x);                 // 1024 blocks
    k_packw<<<(NT * KW * 64) / 256, 256>>>(w);     // 2048 blocks
    k_bgemm<<<MT * NT, 256>>>(out);                // 8192 blocks
}